// round 8
// baseline (speedup 1.0000x reference)
#include <cuda_runtime.h>

#define LSEQ 256
#define CIN  8
#define COUT 8
#define HID  32
#define XPAD 12     // conv arrays: padded row stride (floats), conflict-free LDS.128
#define H1PAD 36    // sh1 row stride: 4-point groups hit disjoint banks for LDS.128
#define NBLK 128
#define NTHR 1024
#define GRP  16     // blocks per o-group

// Scratch: K[o][d][c]
__device__ __align__(16) float g_K[COUT * LSEQ * CIN];
// Per-group barrier state (self-resetting for graph replay)
__device__ volatile unsigned g_bar[COUT] = {0};
__device__ unsigned          g_dep[COUT] = {0};

// ---------------------------------------------------------------------------
// Fused kernel: 128 blocks x 1024 threads, one CTA/SM, 32 warps/SM.
// Phase 1a: cooperative h1 (one sin per value, no redundancy) -> smem.
// Phase 1b: 8 threads/point; each evaluates 4 output neurons from smem h1
//           (hoisted row) + broadcast W2 rows. 3-shfl reduce. No big exchanges.
// Group barrier: 8 groups of 16 blocks (group == out-channel o).
// Phase 2: causal conv from smem; warps 0-15 compute 16 positions.
// ---------------------------------------------------------------------------
__global__ __launch_bounds__(NTHR, 1) void ckconv_fused(
    const float* __restrict__ x,
    const float* __restrict__ v1, const float* __restrict__ g1,
    const float* __restrict__ b1,
    const float* __restrict__ v2, const float* __restrict__ g2,
    const float* __restrict__ b2,
    const float* __restrict__ w3, const float* __restrict__ b3,
    float* __restrict__ out)
{
    __shared__ float  sW1[HID][3];
    __shared__ float  sb1[HID];
    __shared__ float4 sW2[HID][HID / 4];
    __shared__ float  sb2[HID];
    __shared__ float  sw3[HID];
    __shared__ float  sb3;
    __shared__ __align__(16) float sh1[128 * H1PAD];  // h1[point][h], padded
    __shared__ __align__(16) float sk[LSEQ * XPAD];
    __shared__ __align__(16) float sx[LSEQ * XPAD];

    int tid = threadIdx.x;

    // ---------------- phase 0: stage x + weight prep ------------------------
    if (tid < 512) {
        int r = tid >> 1, hh = (tid & 1) << 2;
        *(float4*)&sx[r * XPAD + hh] = ((const float4*)x)[tid];
    }
    if (tid >= 512 && tid < 768) {
        int e = tid - 512;                       // one float4 of v2 per thread
        float4 w4 = ((const float4*)v2)[e];
        float ss = w4.x * w4.x + w4.y * w4.y + w4.z * w4.z + w4.w * w4.w;
        ss += __shfl_xor_sync(0xFFFFFFFFu, ss, 1);
        ss += __shfl_xor_sync(0xFFFFFFFFu, ss, 2);
        ss += __shfl_xor_sync(0xFFFFFFFFu, ss, 4);
        int row = e >> 3;
        float inv = g2[row] * rsqrtf(ss);
        float4 nw;
        nw.x = w4.x * inv; nw.y = w4.y * inv; nw.z = w4.z * inv; nw.w = w4.w * inv;
        ((float4*)sW2)[e] = nw;
    }
    if (tid >= 768 && tid < 768 + HID) {
        int h = tid - 768;
        float a = v1[h * 3 + 0];
        float b = v1[h * 3 + 1];
        float c = v1[h * 3 + 2];
        float inv1 = g1[h] * rsqrtf(a * a + b * b + c * c);
        sW1[h][0] = a * inv1;
        sW1[h][1] = b * inv1;
        sW1[h][2] = c * inv1;
        sb1[h] = b1[h];
        sb2[h] = b2[h];
        sw3[h] = w3[h];
        if (h == 0) sb3 = b3[0];
    }
    __syncthreads();

    // ---------------- point coordinates (8 threads share point p) -----------
    int p   = tid >> 3;                          // local point 0..127
    int q   = tid & 7;
    int pid = blockIdx.x * 128 + p;              // global point
    int c = pid & 7;
    int d = (pid >> 3) & 255;
    int o = pid >> 11;

    float dt = -(float)d * (1.0f / 256.0f);
    float fc = (float)c;
    float fo = (float)o;

    // ---------------- phase 1a: h1 (4 values per thread) --------------------
    {
        float4 hv;
        float* hvp = (float*)&hv;
        #pragma unroll
        for (int m = 0; m < 4; m++) {
            int h = (q << 2) + m;
            float z = fmaf(dt, sW1[h][0], fmaf(fc, sW1[h][1], fmaf(fo, sW1[h][2], sb1[h])));
            hvp[m] = __sinf(z);                  // OMEGA = 1
        }
        *(float4*)&sh1[p * H1PAD + (q << 2)] = hv;
    }
    __syncthreads();

    // ---------------- phase 1b: 4 output neurons per thread -----------------
    float acc;
    {
        // hoist my point's h1 row: 8 float4 (broadcast across the 8 lanes)
        float4 h0 = *(const float4*)&sh1[p * H1PAD + 0];
        float4 h1v = *(const float4*)&sh1[p * H1PAD + 4];
        float4 h2 = *(const float4*)&sh1[p * H1PAD + 8];
        float4 h3 = *(const float4*)&sh1[p * H1PAD + 12];
        float4 h4 = *(const float4*)&sh1[p * H1PAD + 16];
        float4 h5 = *(const float4*)&sh1[p * H1PAD + 20];
        float4 h6 = *(const float4*)&sh1[p * H1PAD + 24];
        float4 h7 = *(const float4*)&sh1[p * H1PAD + 28];

        acc = 0.f;
        #pragma unroll
        for (int m = 0; m < 4; m++) {
            int k = (q << 2) + m;
            const float4* rw = &sW2[k][0];
            float za, zb;
            float4 w;
            w = rw[0];
            za = fmaf(h0.x, w.x, sb2[k]);
            za = fmaf(h0.y, w.y, za);
            za = fmaf(h0.z, w.z, za);
            za = fmaf(h0.w, w.w, za);
            w = rw[1];
            zb = h1v.x * w.x;
            zb = fmaf(h1v.y, w.y, zb);
            zb = fmaf(h1v.z, w.z, zb);
            zb = fmaf(h1v.w, w.w, zb);
            w = rw[2];
            za = fmaf(h2.x, w.x, za);
            za = fmaf(h2.y, w.y, za);
            za = fmaf(h2.z, w.z, za);
            za = fmaf(h2.w, w.w, za);
            w = rw[3];
            zb = fmaf(h3.x, w.x, zb);
            zb = fmaf(h3.y, w.y, zb);
            zb = fmaf(h3.z, w.z, zb);
            zb = fmaf(h3.w, w.w, zb);
            w = rw[4];
            za = fmaf(h4.x, w.x, za);
            za = fmaf(h4.y, w.y, za);
            za = fmaf(h4.z, w.z, za);
            za = fmaf(h4.w, w.w, za);
            w = rw[5];
            zb = fmaf(h5.x, w.x, zb);
            zb = fmaf(h5.y, w.y, zb);
            zb = fmaf(h5.z, w.z, zb);
            zb = fmaf(h5.w, w.w, zb);
            w = rw[6];
            za = fmaf(h6.x, w.x, za);
            za = fmaf(h6.y, w.y, za);
            za = fmaf(h6.z, w.z, za);
            za = fmaf(h6.w, w.w, za);
            w = rw[7];
            zb = fmaf(h7.x, w.x, zb);
            zb = fmaf(h7.y, w.y, zb);
            zb = fmaf(h7.z, w.z, zb);
            zb = fmaf(h7.w, w.w, zb);
            acc = fmaf(__sinf(za + zb), sw3[k], acc);
        }
        // reduce over the 8 lanes sharing this point
        acc += __shfl_xor_sync(0xFFFFFFFFu, acc, 1);
        acc += __shfl_xor_sync(0xFFFFFFFFu, acc, 2);
        acc += __shfl_xor_sync(0xFFFFFFFFu, acc, 4);
    }
    if (q == 0)
        g_K[pid] = acc + sb3;

    // ---------------- group barrier (16 blocks sharing o) -------------------
    int grp = blockIdx.x >> 4;
    __threadfence();
    __syncthreads();
    if (tid == 0) {
        atomicAdd((unsigned*)&g_bar[grp], 1u);
        while (g_bar[grp] < GRP) { }
    }
    __syncthreads();

    // ---------------- phase 2: causal conv ----------------------------------
    int oc   = grp;
    int base = (blockIdx.x & 15) << 4;           // 16 positions per block

    const float4* k4 = (const float4*)(g_K + oc * (LSEQ * CIN));
    if (tid < 512) {
        int r = tid >> 1, hh = (tid & 1) << 2;
        float4 kv = __ldcg(k4 + tid);            // L2-coherent (peer-written)
        *(float4*)&sk[r * XPAD + hh] = kv;
    }
    __syncthreads();

    if (tid < 512) {
        int w = tid >> 5, l = tid & 31;          // warps 0-15 -> 16 positions
        int i = base + w;

        float acc2 = 0.f;
        #pragma unroll
        for (int it = 0; it < 8; it++) {
            if ((it << 5) > i) break;            // warp-uniform early exit
            int dd = l + (it << 5);
            float4 ka = *(const float4*)&sk[dd * XPAD];
            float4 kb = *(const float4*)&sk[dd * XPAD + 4];

            bool v = dd <= i;
            int jc = v ? (i - dd) : 0;
            float m = v ? 1.f : 0.f;

            float4 a0 = *(const float4*)&sx[jc * XPAD];
            float4 b0 = *(const float4*)&sx[jc * XPAD + 4];

            float t = ka.x * a0.x;
            t = fmaf(ka.y, a0.y, t);
            t = fmaf(ka.z, a0.z, t);
            t = fmaf(ka.w, a0.w, t);
            t = fmaf(kb.x, b0.x, t);
            t = fmaf(kb.y, b0.y, t);
            t = fmaf(kb.z, b0.z, t);
            t = fmaf(kb.w, b0.w, t);
            acc2 = fmaf(m, t, acc2);
        }

        #pragma unroll
        for (int s = 16; s > 0; s >>= 1)
            acc2 += __shfl_xor_sync(0xFFFFFFFFu, acc2, s);

        if (l == 0)
            out[i * COUT + oc] = acc2;
    }

    // ---------------- barrier reset (depart counter, replay-safe) -----------
    __syncthreads();
    if (tid == 0) {
        if (atomicAdd(&g_dep[grp], 1u) == GRP - 1u) {
            g_dep[grp] = 0u;
            *(unsigned*)&g_bar[grp] = 0u;
        }
    }
}

// ---------------------------------------------------------------------------
// Launch. Input order: x, t, v1, g1, b1, v2, g2, b2, w3, b3.
// t is the uniform grid arange(L)/L; folded analytically into dt = -d/L.
// ---------------------------------------------------------------------------
extern "C" void kernel_launch(void* const* d_in, const int* in_sizes, int n_in,
                              void* d_out, int out_size)
{
    const float* x  = (const float*)d_in[0];
    const float* v1 = (const float*)d_in[2];
    const float* g1 = (const float*)d_in[3];
    const float* b1 = (const float*)d_in[4];
    const float* v2 = (const float*)d_in[5];
    const float* g2 = (const float*)d_in[6];
    const float* b2 = (const float*)d_in[7];
    const float* w3 = (const float*)d_in[8];
    const float* b3 = (const float*)d_in[9];
    float* out = (float*)d_out;

    ckconv_fused<<<NBLK, NTHR>>>(x, v1, g1, b1, v2, g2, b2, w3, b3, out);
}

// round 9
// speedup vs baseline: 2.0394x; 2.0394x over previous
#include <cuda_runtime.h>

#define LSEQ 256
#define CIN  8
#define COUT 8
#define HID  32
#define XPAD 12     // conv arrays: padded row stride (floats), conflict-free LDS.128
#define H1PAD 36    // sh1 row stride (floats)
#define W2PAD 36    // sW2 row stride (floats): rows land on distinct banks
#define NBLK 128
#define NTHR 1024
#define GRP  16     // blocks per o-group

// Scratch: K[o][d][c]
__device__ __align__(16) float g_K[COUT * LSEQ * CIN];
// Per-group barrier state (self-resetting for graph replay)
__device__ volatile unsigned g_bar[COUT] = {0};
__device__ unsigned          g_dep[COUT] = {0};

// ---------------------------------------------------------------------------
// Fused kernel: 128 blocks x 1024 threads, one CTA/SM, 32 warps/SM.
// Phase 1a: cooperative h1 (one sin per value) -> smem.
// Phase 1b: 8 threads/point; lane q evaluates neurons k = q + 8m (m=0..3).
//           With W2PAD=36, lanes' W2 rows start at banks 4q -> the 8 q-groups
//           tile all 32 banks: every LDS.128 is conflict-free.
// Group barrier: 8 groups of 16 blocks (group == out-channel o).
// Phase 2: causal conv from smem; warps 0-15 compute 16 positions.
// ---------------------------------------------------------------------------
__global__ __launch_bounds__(NTHR, 1) void ckconv_fused(
    const float* __restrict__ x,
    const float* __restrict__ v1, const float* __restrict__ g1,
    const float* __restrict__ b1,
    const float* __restrict__ v2, const float* __restrict__ g2,
    const float* __restrict__ b2,
    const float* __restrict__ w3, const float* __restrict__ b3,
    float* __restrict__ out)
{
    __shared__ float  sW1[HID][3];
    __shared__ float  sb1[HID];
    __shared__ __align__(16) float sW2[HID * W2PAD];   // normalized, padded rows
    __shared__ float  sb2[HID];
    __shared__ float  sw3[HID];
    __shared__ float  sb3;
    __shared__ __align__(16) float sh1[128 * H1PAD];   // h1[point][h]
    __shared__ __align__(16) float sk[LSEQ * XPAD];
    __shared__ __align__(16) float sx[LSEQ * XPAD];

    int tid = threadIdx.x;

    // ---------------- phase 0: stage x + weight prep ------------------------
    if (tid < 512) {
        int r = tid >> 1, hh = (tid & 1) << 2;
        *(float4*)&sx[r * XPAD + hh] = ((const float4*)x)[tid];
    }
    if (tid >= 512 && tid < 768) {
        int e = tid - 512;                       // one float4 of v2 per thread
        float4 w4 = ((const float4*)v2)[e];
        float ss = w4.x * w4.x + w4.y * w4.y + w4.z * w4.z + w4.w * w4.w;
        ss += __shfl_xor_sync(0xFFFFFFFFu, ss, 1);
        ss += __shfl_xor_sync(0xFFFFFFFFu, ss, 2);
        ss += __shfl_xor_sync(0xFFFFFFFFu, ss, 4);
        int row = e >> 3;
        float inv = g2[row] * rsqrtf(ss);
        float4 nw;
        nw.x = w4.x * inv; nw.y = w4.y * inv; nw.z = w4.z * inv; nw.w = w4.w * inv;
        *(float4*)&sW2[row * W2PAD + ((e & 7) << 2)] = nw;
    }
    if (tid >= 768 && tid < 768 + HID) {
        int h = tid - 768;
        float a = v1[h * 3 + 0];
        float b = v1[h * 3 + 1];
        float c = v1[h * 3 + 2];
        float inv1 = g1[h] * rsqrtf(a * a + b * b + c * c);
        sW1[h][0] = a * inv1;
        sW1[h][1] = b * inv1;
        sW1[h][2] = c * inv1;
        sb1[h] = b1[h];
        sb2[h] = b2[h];
        sw3[h] = w3[h];
        if (h == 0) sb3 = b3[0];
    }
    __syncthreads();

    // ---------------- point coordinates (8 threads share point p) -----------
    int p   = tid >> 3;                          // local point 0..127
    int q   = tid & 7;
    int pid = blockIdx.x * 128 + p;              // global point
    int c = pid & 7;
    int d = (pid >> 3) & 255;
    int o = pid >> 11;

    float dt = -(float)d * (1.0f / 256.0f);
    float fc = (float)c;
    float fo = (float)o;

    // ---------------- phase 1a: h1 (4 values per thread) --------------------
    {
        float4 hv;
        float* hvp = (float*)&hv;
        #pragma unroll
        for (int m = 0; m < 4; m++) {
            int h = (q << 2) + m;
            float z = fmaf(dt, sW1[h][0], fmaf(fc, sW1[h][1], fmaf(fo, sW1[h][2], sb1[h])));
            hvp[m] = __sinf(z);                  // OMEGA = 1
        }
        *(float4*)&sh1[p * H1PAD + (q << 2)] = hv;
    }
    __syncthreads();

    // ---------------- phase 1b: neurons k = q + 8m ---------------------------
    float acc;
    {
        const float* h1row = &sh1[p * H1PAD];
        const float* r0 = &sW2[(q     ) * W2PAD];
        const float* r1 = &sW2[(q +  8) * W2PAD];
        const float* r2 = &sW2[(q + 16) * W2PAD];
        const float* r3 = &sW2[(q + 24) * W2PAD];

        float z0 = sb2[q], z1 = sb2[q + 8], z2 = sb2[q + 16], z3 = sb2[q + 24];

        #pragma unroll
        for (int j = 0; j < 8; j++) {
            float4 h  = *(const float4*)&h1row[4 * j];
            float4 w0 = *(const float4*)&r0[4 * j];
            float4 w1 = *(const float4*)&r1[4 * j];
            float4 w2 = *(const float4*)&r2[4 * j];
            float4 w3v = *(const float4*)&r3[4 * j];
            z0 = fmaf(h.x, w0.x, z0); z0 = fmaf(h.y, w0.y, z0);
            z0 = fmaf(h.z, w0.z, z0); z0 = fmaf(h.w, w0.w, z0);
            z1 = fmaf(h.x, w1.x, z1); z1 = fmaf(h.y, w1.y, z1);
            z1 = fmaf(h.z, w1.z, z1); z1 = fmaf(h.w, w1.w, z1);
            z2 = fmaf(h.x, w2.x, z2); z2 = fmaf(h.y, w2.y, z2);
            z2 = fmaf(h.z, w2.z, z2); z2 = fmaf(h.w, w2.w, z2);
            z3 = fmaf(h.x, w3v.x, z3); z3 = fmaf(h.y, w3v.y, z3);
            z3 = fmaf(h.z, w3v.z, z3); z3 = fmaf(h.w, w3v.w, z3);
        }

        acc =       __sinf(z0) * sw3[q];
        acc = fmaf(__sinf(z1), sw3[q + 8],  acc);
        acc = fmaf(__sinf(z2), sw3[q + 16], acc);
        acc = fmaf(__sinf(z3), sw3[q + 24], acc);

        // reduce over the 8 lanes sharing this point
        acc += __shfl_xor_sync(0xFFFFFFFFu, acc, 1);
        acc += __shfl_xor_sync(0xFFFFFFFFu, acc, 2);
        acc += __shfl_xor_sync(0xFFFFFFFFu, acc, 4);
    }
    if (q == 0)
        g_K[pid] = acc + sb3;

    // ---------------- group barrier (16 blocks sharing o) -------------------
    int grp = blockIdx.x >> 4;
    __threadfence();
    __syncthreads();
    if (tid == 0) {
        atomicAdd((unsigned*)&g_bar[grp], 1u);
        while (g_bar[grp] < GRP) { }
    }
    __syncthreads();

    // ---------------- phase 2: causal conv ----------------------------------
    int oc   = grp;
    int base = (blockIdx.x & 15) << 4;           // 16 positions per block

    const float4* k4 = (const float4*)(g_K + oc * (LSEQ * CIN));
    if (tid < 512) {
        int r = tid >> 1, hh = (tid & 1) << 2;
        float4 kv = __ldcg(k4 + tid);            // L2-coherent (peer-written)
        *(float4*)&sk[r * XPAD + hh] = kv;
    }
    __syncthreads();

    if (tid < 512) {
        int w = tid >> 5, l = tid & 31;          // warps 0-15 -> 16 positions
        int i = base + w;

        float acc2 = 0.f;
        #pragma unroll
        for (int it = 0; it < 8; it++) {
            if ((it << 5) > i) break;            // warp-uniform early exit
            int dd = l + (it << 5);
            float4 ka = *(const float4*)&sk[dd * XPAD];
            float4 kb = *(const float4*)&sk[dd * XPAD + 4];

            bool v = dd <= i;
            int jc = v ? (i - dd) : 0;
            float m = v ? 1.f : 0.f;

            float4 a0 = *(const float4*)&sx[jc * XPAD];
            float4 b0 = *(const float4*)&sx[jc * XPAD + 4];

            float t = ka.x * a0.x;
            t = fmaf(ka.y, a0.y, t);
            t = fmaf(ka.z, a0.z, t);
            t = fmaf(ka.w, a0.w, t);
            t = fmaf(kb.x, b0.x, t);
            t = fmaf(kb.y, b0.y, t);
            t = fmaf(kb.z, b0.z, t);
            t = fmaf(kb.w, b0.w, t);
            acc2 = fmaf(m, t, acc2);
        }

        #pragma unroll
        for (int s = 16; s > 0; s >>= 1)
            acc2 += __shfl_xor_sync(0xFFFFFFFFu, acc2, s);

        if (l == 0)
            out[i * COUT + oc] = acc2;
    }

    // ---------------- barrier reset (depart counter, replay-safe) -----------
    __syncthreads();
    if (tid == 0) {
        if (atomicAdd(&g_dep[grp], 1u) == GRP - 1u) {
            g_dep[grp] = 0u;
            *(unsigned*)&g_bar[grp] = 0u;
        }
    }
}

// ---------------------------------------------------------------------------
// Launch. Input order: x, t, v1, g1, b1, v2, g2, b2, w3, b3.
// t is the uniform grid arange(L)/L; folded analytically into dt = -d/L.
// ---------------------------------------------------------------------------
extern "C" void kernel_launch(void* const* d_in, const int* in_sizes, int n_in,
                              void* d_out, int out_size)
{
    const float* x  = (const float*)d_in[0];
    const float* v1 = (const float*)d_in[2];
    const float* g1 = (const float*)d_in[3];
    const float* b1 = (const float*)d_in[4];
    const float* v2 = (const float*)d_in[5];
    const float* g2 = (const float*)d_in[6];
    const float* b2 = (const float*)d_in[7];
    const float* w3 = (const float*)d_in[8];
    const float* b3 = (const float*)d_in[9];
    float* out = (float*)d_out;

    ckconv_fused<<<NBLK, NTHR>>>(x, v1, g1, b1, v2, g2, b2, w3, b3, out);
}

// round 10
// speedup vs baseline: 2.1069x; 1.0331x over previous
#include <cuda_runtime.h>

#define LSEQ 256
#define CIN  8
#define COUT 8
#define HID  32
#define XPAD 12     // conv arrays: padded row stride (floats), conflict-free LDS.128
#define H1PAD 36    // sh1 row stride (floats)
#define W2PAD 36    // sW2 row stride (floats): rows land on distinct banks
#define NBLK 128
#define NTHR 1024
#define GRP  16     // blocks per o-group

// Scratch: K[o][d][c]
__device__ __align__(16) float g_K[COUT * LSEQ * CIN];
// Per-group barrier state (self-resetting for graph replay)
__device__ volatile unsigned g_bar[COUT] = {0};
__device__ unsigned          g_dep[COUT] = {0};

// ---------------------------------------------------------------------------
// Fused kernel: 128 blocks x 1024 threads, one CTA/SM, 32 warps/SM.
// Phase 1a: cooperative h1 (one sin per value) -> smem.
// Phase 1b: 8 threads/point; lane q evaluates neurons k = q + 8m (m=0..3).
//           With W2PAD=36, lanes' W2 rows start at banks 4q -> the 8 q-groups
//           tile all 32 banks: every LDS.128 is conflict-free.
// Group barrier: 8 groups of 16 blocks (group == out-channel o).
// Phase 2: causal conv from smem; warps 0-15 compute 16 positions.
// ---------------------------------------------------------------------------
__global__ __launch_bounds__(NTHR, 1) void ckconv_fused(
    const float* __restrict__ x,
    const float* __restrict__ v1, const float* __restrict__ g1,
    const float* __restrict__ b1,
    const float* __restrict__ v2, const float* __restrict__ g2,
    const float* __restrict__ b2,
    const float* __restrict__ w3, const float* __restrict__ b3,
    float* __restrict__ out)
{
    __shared__ float  sW1[HID][3];
    __shared__ float  sb1[HID];
    __shared__ __align__(16) float sW2[HID * W2PAD];   // normalized, padded rows
    __shared__ float  sb2[HID];
    __shared__ float  sw3[HID];
    __shared__ float  sb3;
    __shared__ __align__(16) float sh1[128 * H1PAD];   // h1[point][h]
    __shared__ __align__(16) float sk[LSEQ * XPAD];
    __shared__ __align__(16) float sx[LSEQ * XPAD];

    int tid = threadIdx.x;

    // ---------------- phase 0: stage x + weight prep ------------------------
    if (tid < 512) {
        int r = tid >> 1, hh = (tid & 1) << 2;
        *(float4*)&sx[r * XPAD + hh] = ((const float4*)x)[tid];
    }
    if (tid >= 512 && tid < 768) {
        int e = tid - 512;                       // one float4 of v2 per thread
        float4 w4 = ((const float4*)v2)[e];
        float ss = w4.x * w4.x + w4.y * w4.y + w4.z * w4.z + w4.w * w4.w;
        ss += __shfl_xor_sync(0xFFFFFFFFu, ss, 1);
        ss += __shfl_xor_sync(0xFFFFFFFFu, ss, 2);
        ss += __shfl_xor_sync(0xFFFFFFFFu, ss, 4);
        int row = e >> 3;
        float inv = g2[row] * rsqrtf(ss);
        float4 nw;
        nw.x = w4.x * inv; nw.y = w4.y * inv; nw.z = w4.z * inv; nw.w = w4.w * inv;
        *(float4*)&sW2[row * W2PAD + ((e & 7) << 2)] = nw;
    }
    if (tid >= 768 && tid < 768 + HID) {
        int h = tid - 768;
        float a = v1[h * 3 + 0];
        float b = v1[h * 3 + 1];
        float c = v1[h * 3 + 2];
        float inv1 = g1[h] * rsqrtf(a * a + b * b + c * c);
        sW1[h][0] = a * inv1;
        sW1[h][1] = b * inv1;
        sW1[h][2] = c * inv1;
        sb1[h] = b1[h];
        sb2[h] = b2[h];
        sw3[h] = w3[h];
        if (h == 0) sb3 = b3[0];
    }
    __syncthreads();

    // ---------------- point coordinates (8 threads share point p) -----------
    int p   = tid >> 3;                          // local point 0..127
    int q   = tid & 7;
    int pid = blockIdx.x * 128 + p;              // global point
    int c = pid & 7;
    int d = (pid >> 3) & 255;
    int o = pid >> 11;

    float dt = -(float)d * (1.0f / 256.0f);
    float fc = (float)c;
    float fo = (float)o;

    // ---------------- phase 1a: h1 (4 values per thread) --------------------
    {
        float4 hv;
        float* hvp = (float*)&hv;
        #pragma unroll
        for (int m = 0; m < 4; m++) {
            int h = (q << 2) + m;
            float z = fmaf(dt, sW1[h][0], fmaf(fc, sW1[h][1], fmaf(fo, sW1[h][2], sb1[h])));
            hvp[m] = __sinf(z);                  // OMEGA = 1
        }
        *(float4*)&sh1[p * H1PAD + (q << 2)] = hv;
    }
    __syncthreads();

    // ---------------- phase 1b: neurons k = q + 8m ---------------------------
    float acc;
    {
        const float* h1row = &sh1[p * H1PAD];
        const float* r0 = &sW2[(q     ) * W2PAD];
        const float* r1 = &sW2[(q +  8) * W2PAD];
        const float* r2 = &sW2[(q + 16) * W2PAD];
        const float* r3 = &sW2[(q + 24) * W2PAD];

        float z0 = sb2[q], z1 = sb2[q + 8], z2 = sb2[q + 16], z3 = sb2[q + 24];

        #pragma unroll
        for (int j = 0; j < 8; j++) {
            float4 h  = *(const float4*)&h1row[4 * j];
            float4 w0 = *(const float4*)&r0[4 * j];
            float4 w1 = *(const float4*)&r1[4 * j];
            float4 w2 = *(const float4*)&r2[4 * j];
            float4 w3v = *(const float4*)&r3[4 * j];
            z0 = fmaf(h.x, w0.x, z0); z0 = fmaf(h.y, w0.y, z0);
            z0 = fmaf(h.z, w0.z, z0); z0 = fmaf(h.w, w0.w, z0);
            z1 = fmaf(h.x, w1.x, z1); z1 = fmaf(h.y, w1.y, z1);
            z1 = fmaf(h.z, w1.z, z1); z1 = fmaf(h.w, w1.w, z1);
            z2 = fmaf(h.x, w2.x, z2); z2 = fmaf(h.y, w2.y, z2);
            z2 = fmaf(h.z, w2.z, z2); z2 = fmaf(h.w, w2.w, z2);
            z3 = fmaf(h.x, w3v.x, z3); z3 = fmaf(h.y, w3v.y, z3);
            z3 = fmaf(h.z, w3v.z, z3); z3 = fmaf(h.w, w3v.w, z3);
        }

        acc =       __sinf(z0) * sw3[q];
        acc = fmaf(__sinf(z1), sw3[q + 8],  acc);
        acc = fmaf(__sinf(z2), sw3[q + 16], acc);
        acc = fmaf(__sinf(z3), sw3[q + 24], acc);

        // reduce over the 8 lanes sharing this point
        acc += __shfl_xor_sync(0xFFFFFFFFu, acc, 1);
        acc += __shfl_xor_sync(0xFFFFFFFFu, acc, 2);
        acc += __shfl_xor_sync(0xFFFFFFFFu, acc, 4);
    }
    if (q == 0)
        g_K[pid] = acc + sb3;

    // ---------------- group barrier (16 blocks sharing o) -------------------
    int grp = blockIdx.x >> 4;
    __threadfence();
    __syncthreads();
    if (tid == 0) {
        atomicAdd((unsigned*)&g_bar[grp], 1u);
        while (g_bar[grp] < GRP) { }
    }
    __syncthreads();

    // ---------------- phase 2: causal conv ----------------------------------
    int oc   = grp;
    int base = (blockIdx.x & 15) << 4;           // 16 positions per block

    const float4* k4 = (const float4*)(g_K + oc * (LSEQ * CIN));
    if (tid < 512) {
        int r = tid >> 1, hh = (tid & 1) << 2;
        float4 kv = __ldcg(k4 + tid);            // L2-coherent (peer-written)
        *(float4*)&sk[r * XPAD + hh] = kv;
    }
    __syncthreads();

    if (tid < 512) {
        int w = tid >> 5, l = tid & 31;          // warps 0-15 -> 16 positions
        int i = base + w;

        float acc2 = 0.f;
        #pragma unroll
        for (int it = 0; it < 8; it++) {
            if ((it << 5) > i) break;            // warp-uniform early exit
            int dd = l + (it << 5);
            float4 ka = *(const float4*)&sk[dd * XPAD];
            float4 kb = *(const float4*)&sk[dd * XPAD + 4];

            bool v = dd <= i;
            int jc = v ? (i - dd) : 0;
            float m = v ? 1.f : 0.f;

            float4 a0 = *(const float4*)&sx[jc * XPAD];
            float4 b0 = *(const float4*)&sx[jc * XPAD + 4];

            float t = ka.x * a0.x;
            t = fmaf(ka.y, a0.y, t);
            t = fmaf(ka.z, a0.z, t);
            t = fmaf(ka.w, a0.w, t);
            t = fmaf(kb.x, b0.x, t);
            t = fmaf(kb.y, b0.y, t);
            t = fmaf(kb.z, b0.z, t);
            t = fmaf(kb.w, b0.w, t);
            acc2 = fmaf(m, t, acc2);
        }

        #pragma unroll
        for (int s = 16; s > 0; s >>= 1)
            acc2 += __shfl_xor_sync(0xFFFFFFFFu, acc2, s);

        if (l == 0)
            out[i * COUT + oc] = acc2;
    }

    // ---------------- barrier reset (depart counter, replay-safe) -----------
    __syncthreads();
    if (tid == 0) {
        if (atomicAdd(&g_dep[grp], 1u) == GRP - 1u) {
            g_dep[grp] = 0u;
            *(unsigned*)&g_bar[grp] = 0u;
        }
    }
}

// ---------------------------------------------------------------------------
// Launch. Input order: x, t, v1, g1, b1, v2, g2, b2, w3, b3.
// t is the uniform grid arange(L)/L; folded analytically into dt = -d/L.
// ---------------------------------------------------------------------------
extern "C" void kernel_launch(void* const* d_in, const int* in_sizes, int n_in,
                              void* d_out, int out_size)
{
    const float* x  = (const float*)d_in[0];
    const float* v1 = (const float*)d_in[2];
    const float* g1 = (const float*)d_in[3];
    const float* b1 = (const float*)d_in[4];
    const float* v2 = (const float*)d_in[5];
    const float* g2 = (const float*)d_in[6];
    const float* b2 = (const float*)d_in[7];
    const float* w3 = (const float*)d_in[8];
    const float* b3 = (const float*)d_in[9];
    float* out = (float*)d_out;

    ckconv_fused<<<NBLK, NTHR>>>(x, v1, g1, b1, v2, g2, b2, w3, b3, out);
}